// round 15
// baseline (speedup 1.0000x reference)
#include <cuda_runtime.h>
#include <cuda_bf16.h>
#include <cstdint>

// ---------------- problem constants ----------------
#define N1v 8192
#define N2v 4096
#define Tv 15
#define Bv 4
#define E1v 131072
#define E2v 65536
#define Kv 12
#define G1v 64
#define G2v 32
#define Cv 6

// ---------------- scratch (device globals; allocation-free) ----------------
__device__ int   d_is64;
__device__ float d_deg1[N1v];
__device__ float d_dinv1[N1v];
__device__ float d_deg2[N2v];
__device__ float d_dinv2[N2v];
__device__ int   d_cnt1[N1v];
__device__ int   d_fill1[N1v];
__device__ int   d_row1[N1v + 1];
__device__ int   d_cnt2[N2v];
__device__ int   d_fill2[N2v];
__device__ int   d_row2[N2v + 1];
__device__ int   d_csrc1[E1v];
__device__ float d_cval1[E1v];
__device__ int   d_csrc2[E2v];
__device__ float d_cval2[E2v];
__device__ float d_P1[2][N1v * 64];          // layer1 Cheb ping-pong, padded [n][64]
__device__ float d_P2[3][Bv][N2v * 64];      // slot0 = h2 (GEMM out); 1,2 ping-pong
__device__ float d_y1[N1v * 256];            // relu(conv1), [n*256 + g*4 + b]
__device__ unsigned short d_y1t_hi[256 * N1v];
__device__ unsigned short d_y1t_lo[256 * N1v];
__device__ unsigned short d_A_hi[(long long)N2v * N1v];
__device__ unsigned short d_A_lo[(long long)N2v * N1v];
__device__ float d_y2[N2v * 128];            // [n*128 + g*4 + b] == torch flat order
__device__ float d_logits[Bv * Cv];
__device__ unsigned int g_bcount[2];
__device__ volatile unsigned int g_bgen[2];

// ================= helpers =================
__device__ __forceinline__ uint32_t smem_to_u32(const void* smem_ptr) {
    uint32_t addr;
    asm("{ .reg .u64 tmp; cvta.to.shared.u64 tmp, %1; cvt.u32.u64 %0, tmp; }"
        : "=r"(addr) : "l"(smem_ptr));
    return addr;
}
__device__ __forceinline__ void ldsm_x4(uint32_t* r, uint32_t addr) {
    asm volatile("ldmatrix.sync.aligned.m8n8.x4.shared.b16 {%0,%1,%2,%3}, [%4];"
        : "=r"(r[0]), "=r"(r[1]), "=r"(r[2]), "=r"(r[3]) : "r"(addr));
}
__device__ __forceinline__ void ldsm_x2(uint32_t* r, uint32_t addr) {
    asm volatile("ldmatrix.sync.aligned.m8n8.x2.shared.b16 {%0,%1}, [%2];"
        : "=r"(r[0]), "=r"(r[1]) : "r"(addr));
}
__device__ __forceinline__ void mma_bf16(float* c, const uint32_t* a, const uint32_t* b) {
    asm volatile(
        "mma.sync.aligned.m16n8k16.row.col.f32.bf16.bf16.f32 "
        "{%0,%1,%2,%3}, {%4,%5,%6,%7}, {%8,%9}, {%0,%1,%2,%3};"
        : "+f"(c[0]), "+f"(c[1]), "+f"(c[2]), "+f"(c[3])
        : "r"(a[0]), "r"(a[1]), "r"(a[2]), "r"(a[3]), "r"(b[0]), "r"(b[1]));
}
__device__ __forceinline__ void cp16(uint32_t s, const void* g) {
    asm volatile("cp.async.cg.shared.global [%0], [%1], 16;" :: "r"(s), "l"(g) : "memory");
}
#define CP_COMMIT() asm volatile("cp.async.commit_group;" ::: "memory")
#define CP_WAIT2()  asm volatile("cp.async.wait_group 2;" ::: "memory")

__device__ __forceinline__ void grid_barrier(int id) {
    __syncthreads();
    if (threadIdx.x == 0) {
        __threadfence();
        unsigned int gen = g_bgen[id];
        if (atomicAdd(&g_bcount[id], 1u) == gridDim.x - 1) {
            g_bcount[id] = 0;
            __threadfence();
            g_bgen[id] = gen + 1;
        } else {
            while (g_bgen[id] == gen) { __nanosleep(64); }
        }
        __threadfence();
    }
    __syncthreads();
}

__device__ __forceinline__ int load_idx(const void* ei, int pos, int is64) {
    if (is64) return (int)((const long long*)ei)[pos];
    return ((const int*)ei)[pos];
}
__device__ __forceinline__ uint32_t pack_bf2(__nv_bfloat16 a, __nv_bfloat16 b) {
    return ((uint32_t)__bfloat16_as_ushort(b) << 16) | (uint32_t)__bfloat16_as_ushort(a);
}

// ---------------- fused zero + dtype detect ----------------
__global__ void zero_detect_kernel(const int* __restrict__ ei1_i32) {
    int i = blockIdx.x * 256 + threadIdx.x;
    if (i < N2v * 64 * Bv) ((float*)d_P2)[i] = 0.0f;   // slot0 (GEMM accum target)
    if (i < N1v) { d_deg1[i] = 0.0f; d_cnt1[i] = 0; d_fill1[i] = 0; }
    if (i < N2v) { d_deg2[i] = 0.0f; d_cnt2[i] = 0; d_fill2[i] = 0; }
    if (i < Bv * Cv) d_logits[i] = 0.0f;
    if (i == 0) {
        int is64 = 1;
        for (int j = 1; j < 64; j += 2)
            if (ei1_i32[j] != 0) { is64 = 0; break; }
        d_is64 = is64;
    }
}

// ---------------- b_map -> bf16 hi/lo (one pass, HBM-bound) ----------------
__global__ void aconv_kernel(const float* __restrict__ A) {
    long long i = ((long long)blockIdx.x * 256 + threadIdx.x) * 4;
    float4 v = __ldg((const float4*)(A + i));
    __nv_bfloat16 h0 = __float2bfloat16(v.x);
    __nv_bfloat16 h1 = __float2bfloat16(v.y);
    __nv_bfloat16 h2 = __float2bfloat16(v.z);
    __nv_bfloat16 h3 = __float2bfloat16(v.w);
    __nv_bfloat16 l0 = __float2bfloat16(v.x - __bfloat162float(h0));
    __nv_bfloat16 l1 = __float2bfloat16(v.y - __bfloat162float(h1));
    __nv_bfloat16 l2 = __float2bfloat16(v.z - __bfloat162float(h2));
    __nv_bfloat16 l3 = __float2bfloat16(v.w - __bfloat162float(h3));
    *(uint2*)((char*)d_A_hi + i * 2) = make_uint2(pack_bf2(h0, h1), pack_bf2(h2, h3));
    *(uint2*)((char*)d_A_lo + i * 2) = make_uint2(pack_bf2(l0, l1), pack_bf2(l2, l3));
}

// ---------------- fused degree kernels ----------------
__global__ void deg12_kernel(const void* __restrict__ ei1, const float* __restrict__ w1,
                             const void* __restrict__ ei2, const float* __restrict__ w2) {
    int i = blockIdx.x * 256 + threadIdx.x;
    int is64 = d_is64;
    if (i < E1v) {
        int d = load_idx(ei1, E1v + i, is64);
        if ((unsigned)d < N1v) { atomicAdd(&d_deg1[d], w1[i]); atomicAdd(&d_cnt1[d], 1); }
    } else if (i < E1v + E2v) {
        int e = i - E1v;
        int d = load_idx(ei2, E2v + e, is64);
        if ((unsigned)d < N2v) { atomicAdd(&d_deg2[d], w2[e]); atomicAdd(&d_cnt2[d], 1); }
    }
}

__global__ void dinv_kernel() {
    int i = blockIdx.x * 256 + threadIdx.x;
    if (i < N1v) { float v = d_deg1[i]; d_dinv1[i] = (v > 0.0f) ? rsqrtf(v) : 0.0f; }
    if (i < N2v) { float v = d_deg2[i]; d_dinv2[i] = (v > 0.0f) ? rsqrtf(v) : 0.0f; }
}

__global__ void scan_kernel() {
    __shared__ int sh[1024];
    int tid = threadIdx.x;
    {
        int v[8]; int s = 0;
#pragma unroll
        for (int j = 0; j < 8; j++) { v[j] = d_cnt1[tid * 8 + j]; s += v[j]; }
        sh[tid] = s; __syncthreads();
        for (int off = 1; off < 1024; off <<= 1) {
            int x = (tid >= off) ? sh[tid - off] : 0;
            __syncthreads();
            sh[tid] += x;
            __syncthreads();
        }
        int run = sh[tid] - s;
#pragma unroll
        for (int j = 0; j < 8; j++) { d_row1[tid * 8 + j] = run; run += v[j]; }
        if (tid == 1023) d_row1[N1v] = run;
    }
    __syncthreads();
    {
        int v[4]; int s = 0;
#pragma unroll
        for (int j = 0; j < 4; j++) { v[j] = d_cnt2[tid * 4 + j]; s += v[j]; }
        sh[tid] = s; __syncthreads();
        for (int off = 1; off < 1024; off <<= 1) {
            int x = (tid >= off) ? sh[tid - off] : 0;
            __syncthreads();
            sh[tid] += x;
            __syncthreads();
        }
        int run = sh[tid] - s;
#pragma unroll
        for (int j = 0; j < 4; j++) { d_row2[tid * 4 + j] = run; run += v[j]; }
        if (tid == 1023) d_row2[N2v] = run;
    }
}

__global__ void fill12_kernel(const void* __restrict__ ei1, const float* __restrict__ w1,
                              const void* __restrict__ ei2, const float* __restrict__ w2) {
    int i = blockIdx.x * 256 + threadIdx.x;
    int is64 = d_is64;
    if (i < E1v) {
        int s = load_idx(ei1, i, is64);
        int d = load_idx(ei1, E1v + i, is64);
        if ((unsigned)s < N1v && (unsigned)d < N1v) {
            float v = -w1[i] * d_dinv1[s] * d_dinv1[d];
            int p = d_row1[d] + atomicAdd(&d_fill1[d], 1);
            if ((unsigned)p < E1v) { d_csrc1[p] = s; d_cval1[p] = v; }
        }
    } else if (i < E1v + E2v) {
        int e = i - E1v;
        int s = load_idx(ei2, e, is64);
        int d = load_idx(ei2, E2v + e, is64);
        if ((unsigned)s < N2v && (unsigned)d < N2v) {
            float v = -w2[e] * d_dinv2[s] * d_dinv2[d];
            int p = d_row2[d] + atomicAdd(&d_fill2[d], 1);
            if ((unsigned)p < E2v) { d_csrc2[p] = s; d_cval2[p] = v; }
        }
    }
}

// ---------------- persistent fused layer 1: transpose + 11 props + einsum1 ----------------
// grid 256 x 256 threads, 2 blocks/SM (all resident). Each block owns 32 nodes.
// Einsum accumulators in registers: thread = (n_l=tid>>3, b=(tid>>1)&3, gh=tid&1) -> 32 g.
#define L1_SMEM ((Kv * Tv * G1v + 32 * 65) * 4)   // 46080 + 8320 = 54400 B

__global__ void __launch_bounds__(256, 2) layer1_fused(
        const float* __restrict__ x, const float* __restrict__ W1,
        const float* __restrict__ b1) {
    extern __shared__ float sm1[];
    float* sW = sm1;                       // [k][t][g] : 11520
    float* sT = sm1 + Kv * Tv * G1v;       // [n_l][65]
    int tid = threadIdx.x;
    int nbase = blockIdx.x * 32;
    int ty = tid >> 6, tx = tid & 63;      // gather: node = nbase + j*4 + ty, comp c = tx
    int a_nl = tid >> 3, a_b = (tid >> 1) & 3, a_gh = tid & 1;

    for (int i = tid; i < Kv * Tv * G1v; i += 256) sW[i] = W1[i];

    float4 acc[8];
#pragma unroll
    for (int q = 0; q < 8; q++) acc[q] = make_float4(0.f, 0.f, 0.f, 0.f);
    float pv1[8], pv2[8];

    // ---- k = 0: T_0 = x transposed ----
#pragma unroll
    for (int j = 0; j < 8; j++) {
        int n = nbase + j * 4 + ty;
        float v = 0.0f;
        if (tx < 60) v = __ldg(&x[(tx & 3) * (N1v * Tv) + n * Tv + (tx >> 2)]);
        d_P1[0][n * 64 + tx] = v;
        sT[(j * 4 + ty) * 65 + tx] = v;
        pv1[j] = v; pv2[j] = 0.0f;
    }
    __syncthreads();
    {
        const float* wk = sW;
#pragma unroll
        for (int t = 0; t < Tv; t++) {
            float v = sT[a_nl * 65 + t * 4 + a_b];
            const float4* w4 = (const float4*)(wk + t * 64 + a_gh * 32);
#pragma unroll
            for (int q = 0; q < 8; q++) {
                float4 w = w4[q];
                acc[q].x += v * w.x; acc[q].y += v * w.y;
                acc[q].z += v * w.z; acc[q].w += v * w.w;
            }
        }
    }

    // ---- k = 1..11 ----
    for (int k = 1; k < Kv; k++) {
        grid_barrier(0);
        const float* __restrict__ prev = d_P1[(k - 1) & 1];
        float* cur = d_P1[k & 1];
#pragma unroll
        for (int j = 0; j < 8; j++) {
            int n = nbase + j * 4 + ty;
            int beg = d_row1[n], end = d_row1[n + 1];
            float g = 0.0f;
            int e = beg;
            for (; e + 4 <= end; e += 4) {
                int s0 = d_csrc1[e],     s1 = d_csrc1[e + 1];
                int s2 = d_csrc1[e + 2], s3 = d_csrc1[e + 3];
                float w0 = d_cval1[e],     w1_ = d_cval1[e + 1];
                float w2_ = d_cval1[e + 2], w3_ = d_cval1[e + 3];
                g += w0 * prev[s0 * 64 + tx] + w1_ * prev[s1 * 64 + tx]
                   + w2_ * prev[s2 * 64 + tx] + w3_ * prev[s3 * 64 + tx];
            }
            for (; e < end; e++) g += d_cval1[e] * prev[d_csrc1[e] * 64 + tx];
            float v = (k == 1) ? g : 2.0f * g - pv2[j];
            pv2[j] = pv1[j]; pv1[j] = v;
            cur[n * 64 + tx] = v;
            sT[(j * 4 + ty) * 65 + tx] = v;
        }
        __syncthreads();
        const float* wk = sW + k * (Tv * G1v);
#pragma unroll
        for (int t = 0; t < Tv; t++) {
            float v = sT[a_nl * 65 + t * 4 + a_b];
            const float4* w4 = (const float4*)(wk + t * 64 + a_gh * 32);
#pragma unroll
            for (int q = 0; q < 8; q++) {
                float4 w = w4[q];
                acc[q].x += v * w.x; acc[q].y += v * w.y;
                acc[q].z += v * w.z; acc[q].w += v * w.w;
            }
        }
    }

    // ---- finalize: bias + relu -> y1 ----
    int n = nbase + a_nl;
    float* yp = d_y1 + n * 256 + a_b;
#pragma unroll
    for (int q = 0; q < 8; q++) {
        int g0 = a_gh * 32 + q * 4;
        yp[(g0 + 0) * 4] = fmaxf(acc[q].x + b1[g0 + 0], 0.0f);
        yp[(g0 + 1) * 4] = fmaxf(acc[q].y + b1[g0 + 1], 0.0f);
        yp[(g0 + 2) * 4] = fmaxf(acc[q].z + b1[g0 + 2], 0.0f);
        yp[(g0 + 3) * 4] = fmaxf(acc[q].w + b1[g0 + 3], 0.0f);
    }
}

// ---------------- y1 -> transposed bf16 hi/lo split ----------------
__global__ void y1split_kernel() {
    __shared__ float tile[32][33];
    int k0 = blockIdx.x * 32, c0 = blockIdx.y * 32;
    int tx = threadIdx.x, ty = threadIdx.y;   // 32 x 8
#pragma unroll
    for (int i = 0; i < 4; i++)
        tile[ty + 8 * i][tx] = d_y1[(k0 + ty + 8 * i) * 256 + c0 + tx];
    __syncthreads();
#pragma unroll
    for (int i = 0; i < 4; i++) {
        int c = c0 + ty + 8 * i;
        float v = tile[tx][ty + 8 * i];
        __nv_bfloat16 h = __float2bfloat16(v);
        float lo = v - __bfloat162float(h);
        long long idx = (long long)c * N1v + k0 + tx;
        d_y1t_hi[idx] = __bfloat16_as_ushort(h);
        d_y1t_lo[idx] = __bfloat16_as_ushort(__float2bfloat16(lo));
    }
}

// ---------------- warp-MMA pooling GEMM (cp.async 3-stage pipeline) ----------------
#define KSPLIT 2
#define KB2 64
#define ASTRIDE 72
#define MAT_BYTES (128 * ASTRIDE * 2)
#define STG_BYTES (4 * MAT_BYTES)
#define NSTAGE 3
#define SMEM_GEMM_TOTAL (NSTAGE * STG_BYTES)   // 221184

__device__ __forceinline__ void fill_async(uint32_t sbase, int s, int m0, int n0, int kblk) {
    int t = threadIdx.x;
    uint32_t ah = sbase + s * STG_BYTES;
    uint32_t al = ah + MAT_BYTES;
    uint32_t bh = al + MAT_BYTES;
    uint32_t bl = bh + MAT_BYTES;
#pragma unroll
    for (int i = 0; i < 4; i++) {
        int idx = t + 256 * i;
        int r = idx >> 3, c = (idx & 7) * 8;
        uint32_t so = (uint32_t)(r * ASTRIDE + c) * 2;
        long long ka = ((long long)(m0 + r) * N1v + kblk + c) * 2;
        cp16(ah + so, (const char*)d_A_hi + ka);
        cp16(al + so, (const char*)d_A_lo + ka);
        long long kb = ((long long)(n0 + r) * N1v + kblk + c) * 2;
        cp16(bh + so, (const char*)d_y1t_hi + kb);
        cp16(bl + so, (const char*)d_y1t_lo + kb);
    }
}

__global__ void __launch_bounds__(256, 1) pool_gemm_mma() {
    extern __shared__ __align__(16) char smem[];
    uint32_t sbase = smem_to_u32(smem);
    int tid = threadIdx.x, wid = tid >> 5, lid = tid & 31;
    int m0 = blockIdx.y * 128, n0 = blockIdx.z * 128;
    int kbase = blockIdx.x * (N1v / KSPLIT);
    const int NB = (N1v / KSPLIT) / KB2;      // 64
    int wm = (wid >> 1) * 32;
    int wn = (wid & 1) * 64;

    float acc[2][8][4];
#pragma unroll
    for (int mt = 0; mt < 2; mt++)
#pragma unroll
        for (int nt = 0; nt < 8; nt++)
#pragma unroll
            for (int q = 0; q < 4; q++) acc[mt][nt][q] = 0.0f;

    int arow = wm + (lid & 15);
    int acol = (lid >> 4) * 8;
    int l16 = lid & 15;
    int brow = wn + (l16 & 7);
    int bcol = ((l16 >> 3) & 1) * 8;

    fill_async(sbase, 0, m0, n0, kbase);            CP_COMMIT();
    fill_async(sbase, 1, m0, n0, kbase + KB2);      CP_COMMIT();
    fill_async(sbase, 2, m0, n0, kbase + 2 * KB2);  CP_COMMIT();

    for (int it = 0; it < NB; it++) {
        CP_WAIT2();
        __syncthreads();
        int s = it % NSTAGE;
        uint32_t aHiB = sbase + s * STG_BYTES;
        uint32_t aLoB = aHiB + MAT_BYTES;
        uint32_t bHiB = aLoB + MAT_BYTES;
        uint32_t bLoB = bHiB + MAT_BYTES;
#pragma unroll
        for (int k16 = 0; k16 < KB2 / 16; k16++) {
            uint32_t ah[2][4], alo[2][4], bhf[8][2], blf[8][2];
#pragma unroll
            for (int mt = 0; mt < 2; mt++) {
                uint32_t off = (uint32_t)(((arow + mt * 16) * ASTRIDE + k16 * 16 + acol) * 2);
                ldsm_x4(ah[mt],  aHiB + off);
                ldsm_x4(alo[mt], aLoB + off);
            }
#pragma unroll
            for (int nt = 0; nt < 8; nt++) {
                uint32_t off = (uint32_t)(((brow + nt * 8) * ASTRIDE + k16 * 16 + bcol) * 2);
                ldsm_x2(bhf[nt], bHiB + off);
                ldsm_x2(blf[nt], bLoB + off);
            }
#pragma unroll
            for (int mt = 0; mt < 2; mt++)
#pragma unroll
                for (int nt = 0; nt < 8; nt++) {
                    mma_bf16(acc[mt][nt], ah[mt],  bhf[nt]);
                    mma_bf16(acc[mt][nt], alo[mt], bhf[nt]);
                    mma_bf16(acc[mt][nt], ah[mt],  blf[nt]);
                }
        }
        __syncthreads();
        if (it + NSTAGE < NB)
            fill_async(sbase, s, m0, n0, kbase + (it + NSTAGE) * KB2);
        CP_COMMIT();
    }

    // epilogue: atomic-accumulate into d_P2 slot0 ([b][m][g], col = g*4+b)
#pragma unroll
    for (int mt = 0; mt < 2; mt++) {
        int m_lo = m0 + wm + mt * 16 + (lid >> 2);
        int m_hi = m_lo + 8;
#pragma unroll
        for (int nt = 0; nt < 8; nt++) {
            int c0 = n0 + wn + nt * 8 + (lid & 3) * 2;
            int c1 = c0 + 1;
            atomicAdd(&d_P2[0][c0 & 3][m_lo * 64 + (c0 >> 2)], acc[mt][nt][0]);
            atomicAdd(&d_P2[0][c1 & 3][m_lo * 64 + (c1 >> 2)], acc[mt][nt][1]);
            atomicAdd(&d_P2[0][c0 & 3][m_hi * 64 + (c0 >> 2)], acc[mt][nt][2]);
            atomicAdd(&d_P2[0][c1 & 3][m_hi * 64 + (c1 >> 2)], acc[mt][nt][3]);
        }
    }
}

// ---------------- persistent fused layer 2: 11 props + einsum2 ----------------
// grid 256 x 256 threads, 2 blocks/SM. Each block owns 16 nodes.
// thread = (n_l=tid>>4, u=tid&15: b=u&3, gq=u>>2) -> 8 g accumulators.
__global__ void __launch_bounds__(256, 2) layer2_fused(
        const float* __restrict__ W2, const float* __restrict__ b2) {
    __shared__ float sT[16 * 4 * 65];     // [(n_l*4+b)][65]
    __shared__ float sW[64 * 32];         // one k slice
    int tid = threadIdx.x;
    int nbase = blockIdx.x * 16;
    int ty = tid >> 6, tx = tid & 63;     // gather: node = nbase + j*4 + ty, d = tx
    int a_nl = tid >> 4, a_u = tid & 15;
    int a_b = a_u & 3, a_gq = a_u >> 2;

    float acc8[8];
#pragma unroll
    for (int q = 0; q < 8; q++) acc8[q] = 0.0f;
    float pv1[16], pv2[16];

    // ---- k = 0: h2 from slot0 ----
#pragma unroll
    for (int j = 0; j < 4; j++)
#pragma unroll
        for (int bs = 0; bs < 4; bs++) {
            int n = nbase + j * 4 + ty;
            float v = d_P2[0][bs][n * 64 + tx];
            sT[((j * 4 + ty) * 4 + bs) * 65 + tx] = v;
            pv1[j * 4 + bs] = v; pv2[j * 4 + bs] = 0.0f;
        }
    for (int i = tid; i < 2048; i += 256) sW[i] = W2[i];
    __syncthreads();
#pragma unroll
    for (int d = 0; d < 64; d++) {
        float v = sT[(a_nl * 4 + a_b) * 65 + d];
        const float4* w4 = (const float4*)(sW + d * 32 + a_gq * 8);
        float4 wa = w4[0], wb = w4[1];
        acc8[0] += v * wa.x; acc8[1] += v * wa.y; acc8[2] += v * wa.z; acc8[3] += v * wa.w;
        acc8[4] += v * wb.x; acc8[5] += v * wb.y; acc8[6] += v * wb.z; acc8[7] += v * wb.w;
    }

    // ---- k = 1..11 ----
    for (int k = 1; k < Kv; k++) {
        grid_barrier(1);
        int ps = (k == 1) ? 0 : (((k - 1) & 1) ? 1 : 2);
        int cs = (k & 1) ? 1 : 2;
#pragma unroll
        for (int j = 0; j < 4; j++)
#pragma unroll
            for (int bs = 0; bs < 4; bs++) {
                int n = nbase + j * 4 + ty;
                const float* __restrict__ prev = d_P2[ps][bs];
                int beg = d_row2[n], end = d_row2[n + 1];
                float g = 0.0f;
                int e = beg;
                for (; e + 4 <= end; e += 4) {
                    int s0 = d_csrc2[e],     s1 = d_csrc2[e + 1];
                    int s2 = d_csrc2[e + 2], s3 = d_csrc2[e + 3];
                    float w0 = d_cval2[e],     w1_ = d_cval2[e + 1];
                    float w2_ = d_cval2[e + 2], w3_ = d_cval2[e + 3];
                    g += w0 * prev[s0 * 64 + tx] + w1_ * prev[s1 * 64 + tx]
                       + w2_ * prev[s2 * 64 + tx] + w3_ * prev[s3 * 64 + tx];
                }
                for (; e < end; e++) g += d_cval2[e] * prev[d_csrc2[e] * 64 + tx];
                float v = (k == 1) ? g : 2.0f * g - pv2[j * 4 + bs];
                pv2[j * 4 + bs] = pv1[j * 4 + bs]; pv1[j * 4 + bs] = v;
                d_P2[cs][bs][n * 64 + tx] = v;
                sT[((j * 4 + ty) * 4 + bs) * 65 + tx] = v;
            }
        __syncthreads();
        for (int i = tid; i < 2048; i += 256) sW[i] = W2[k * 2048 + i];
        __syncthreads();
#pragma unroll
        for (int d = 0; d < 64; d++) {
            float v = sT[(a_nl * 4 + a_b) * 65 + d];
            const float4* w4 = (const float4*)(sW + d * 32 + a_gq * 8);
            float4 wa = w4[0], wb = w4[1];
            acc8[0] += v * wa.x; acc8[1] += v * wa.y; acc8[2] += v * wa.z; acc8[3] += v * wa.w;
            acc8[4] += v * wb.x; acc8[5] += v * wb.y; acc8[6] += v * wb.z; acc8[7] += v * wb.w;
        }
    }

    // ---- finalize: + bias -> y2 ----
    int n = nbase + a_nl;
#pragma unroll
    for (int q = 0; q < 8; q++) {
        int g = a_gq * 8 + q;
        d_y2[n * 128 + g * 4 + a_b] = acc8[q] + b2[g];
    }
}

// ---------------- FC (split-K) + log_softmax ----------------
__global__ void fc_kernel(const float* __restrict__ fcw) {
    int bc = blockIdx.x;
    int b = bc / 6, c = bc - b * 6;
    int ks = blockIdx.y;
    const float4* w4 = (const float4*)(fcw + (long long)c * 131072);
    const float4* h4 = (const float4*)(d_y2 + b * 131072);
    float s = 0.0f;
    int beg = ks * 4096, end = beg + 4096;
    for (int i = beg + threadIdx.x; i < end; i += 256) {
        float4 a = __ldg(&w4[i]);
        float4 h = h4[i];
        s += a.x * h.x + a.y * h.y + a.z * h.z + a.w * h.w;
    }
    __shared__ float sh[256];
    sh[threadIdx.x] = s;
    __syncthreads();
    for (int off = 128; off > 0; off >>= 1) {
        if (threadIdx.x < off) sh[threadIdx.x] += sh[threadIdx.x + off];
        __syncthreads();
    }
    if (threadIdx.x == 0) atomicAdd(&d_logits[bc], sh[0]);
}

__global__ void lsm_kernel(float* __restrict__ out, const float* __restrict__ fcb) {
    int b = threadIdx.x;
    if (b < Bv) {
        float l[Cv];
        float m = -1e30f;
#pragma unroll
        for (int c = 0; c < Cv; c++) { l[c] = d_logits[b * Cv + c] + fcb[c]; m = fmaxf(m, l[c]); }
        float s = 0.0f;
#pragma unroll
        for (int c = 0; c < Cv; c++) s += expf(l[c] - m);
        float L = logf(s);
#pragma unroll
        for (int c = 0; c < Cv; c++) out[b * Cv + c] = l[c] - m - L;
    }
}

// ---------------- launch ----------------
extern "C" void kernel_launch(void* const* d_in, const int* in_sizes, int n_in,
                              void* d_out, int out_size) {
    const float* x    = (const float*)d_in[0];
    const void*  ei1  = d_in[1];
    const float* ew1  = (const float*)d_in[2];
    const void*  ei2  = d_in[3];
    const float* ew2  = (const float*)d_in[4];
    const float* bmap = (const float*)d_in[5];
    const float* W1   = (const float*)d_in[6];
    const float* b1   = (const float*)d_in[7];
    const float* W2   = (const float*)d_in[8];
    const float* b2   = (const float*)d_in[9];
    const float* fcw  = (const float*)d_in[10];
    const float* fcb  = (const float*)d_in[11];
    float* out = (float*)d_out;

    cudaFuncSetAttribute(pool_gemm_mma, cudaFuncAttributeMaxDynamicSharedMemorySize,
                         SMEM_GEMM_TOTAL);
    cudaFuncSetAttribute(layer1_fused, cudaFuncAttributeMaxDynamicSharedMemorySize,
                         L1_SMEM);

    zero_detect_kernel<<<(N2v * 64 * Bv) / 256, 256>>>((const int*)ei1);
    aconv_kernel<<<32768, 256>>>(bmap);
    deg12_kernel<<<(E1v + E2v) / 256, 256>>>(ei1, ew1, ei2, ew2);
    dinv_kernel<<<N1v / 256, 256>>>();
    scan_kernel<<<1, 1024>>>();
    fill12_kernel<<<(E1v + E2v) / 256, 256>>>(ei1, ew1, ei2, ew2);

    layer1_fused<<<256, 256, L1_SMEM>>>(x, W1, b1);
    y1split_kernel<<<dim3(N1v / 32, 256 / 32), dim3(32, 8)>>>();
    pool_gemm_mma<<<dim3(KSPLIT, 32, 2), 256, SMEM_GEMM_TOTAL>>>();
    layer2_fused<<<256, 256>>>(W2, b2);

    fc_kernel<<<dim3(Bv * Cv, 8), 256>>>(fcw);
    lsm_kernel<<<1, 32>>>(out, fcb);
}

// round 16
// speedup vs baseline: 1.2159x; 1.2159x over previous
#include <cuda_runtime.h>
#include <cuda_bf16.h>
#include <cstdint>

// ---------------- problem constants ----------------
#define N1v 8192
#define N2v 4096
#define Tv 15
#define Bv 4
#define E1v 131072
#define E2v 65536
#define Kv 12
#define G1v 64
#define G2v 32
#define Cv 6

#define D1v 60                    // T*B comps per node, layer1 (layout t*4+b)
#define T1_SLOT (N1v * D1v)       // 491520
#define T2_SLOT (N2v * 64 * Bv)   // 1048576, layout [b][n][g]
#define T2_BOFF (N2v * 64)        // 262144

// ---------------- scratch (device globals; allocation-free) ----------------
__device__ int   d_is64;
__device__ float d_deg1[N1v];
__device__ float d_dinv1[N1v];
__device__ float d_deg2[N2v];
__device__ float d_dinv2[N2v];
__device__ int   d_cnt1[N1v];
__device__ int   d_fill1[N1v];
__device__ int   d_row1[N1v + 1];
__device__ int   d_cnt2[N2v];
__device__ int   d_fill2[N2v];
__device__ int   d_row2[N2v + 1];
__device__ int   d_csrc1[E1v];
__device__ float d_cval1[E1v];
__device__ int   d_csrc2[E2v];
__device__ float d_cval2[E2v];
__device__ float d_T1[Kv * T1_SLOT];    // Cheb tensors layer1, [k][n*60 + t*4 + b]
__device__ float d_y1[N1v * 256];       // relu(conv1), [n*256 + g*4 + b]
__device__ unsigned short d_y1t_hi[256 * N1v];   // y1^T hi bf16, [col][k]
__device__ unsigned short d_y1t_lo[256 * N1v];   // y1^T lo bf16, [col][k]
__device__ unsigned short d_A_hi[(long long)N2v * N1v];   // b_map hi bf16
__device__ unsigned short d_A_lo[(long long)N2v * N1v];   // b_map lo bf16
__device__ float d_T2g[Kv * T2_SLOT];   // Cheb tensors layer2, [k][b][n][g]
__device__ float d_y2[N2v * 128];       // conv2 out, [n*128 + g*4 + b] (== torch flat order)
__device__ float d_logits[Bv * Cv];
__device__ unsigned int g_bcount[2];
__device__ volatile unsigned int g_bgen[2];

// ================= helpers =================
__device__ __forceinline__ uint32_t smem_to_u32(const void* smem_ptr) {
    uint32_t addr;
    asm("{ .reg .u64 tmp; cvta.to.shared.u64 tmp, %1; cvt.u32.u64 %0, tmp; }"
        : "=r"(addr) : "l"(smem_ptr));
    return addr;
}
__device__ __forceinline__ void ldsm_x4(uint32_t* r, uint32_t addr) {
    asm volatile("ldmatrix.sync.aligned.m8n8.x4.shared.b16 {%0,%1,%2,%3}, [%4];"
        : "=r"(r[0]), "=r"(r[1]), "=r"(r[2]), "=r"(r[3]) : "r"(addr));
}
__device__ __forceinline__ void ldsm_x2(uint32_t* r, uint32_t addr) {
    asm volatile("ldmatrix.sync.aligned.m8n8.x2.shared.b16 {%0,%1}, [%2];"
        : "=r"(r[0]), "=r"(r[1]) : "r"(addr));
}
__device__ __forceinline__ void mma_bf16(float* c, const uint32_t* a, const uint32_t* b) {
    asm volatile(
        "mma.sync.aligned.m16n8k16.row.col.f32.bf16.bf16.f32 "
        "{%0,%1,%2,%3}, {%4,%5,%6,%7}, {%8,%9}, {%0,%1,%2,%3};"
        : "+f"(c[0]), "+f"(c[1]), "+f"(c[2]), "+f"(c[3])
        : "r"(a[0]), "r"(a[1]), "r"(a[2]), "r"(a[3]), "r"(b[0]), "r"(b[1]));
}
__device__ __forceinline__ void cp16(uint32_t s, const void* g) {
    asm volatile("cp.async.cg.shared.global [%0], [%1], 16;" :: "r"(s), "l"(g) : "memory");
}
#define CP_COMMIT() asm volatile("cp.async.commit_group;" ::: "memory")
#define CP_WAIT2()  asm volatile("cp.async.wait_group 2;" ::: "memory")

__device__ __forceinline__ void grid_barrier(int id) {
    __syncthreads();
    if (threadIdx.x == 0) {
        __threadfence();
        unsigned int gen = g_bgen[id];
        if (atomicAdd(&g_bcount[id], 1u) == gridDim.x - 1) {
            g_bcount[id] = 0;
            __threadfence();
            g_bgen[id] = gen + 1;
        } else {
            while (g_bgen[id] == gen) { __nanosleep(64); }
        }
        __threadfence();
    }
    __syncthreads();
}

__device__ __forceinline__ int load_idx(const void* ei, int pos, int is64) {
    if (is64) return (int)((const long long*)ei)[pos];
    return ((const int*)ei)[pos];
}
__device__ __forceinline__ uint32_t pack_bf2(__nv_bfloat16 a, __nv_bfloat16 b) {
    return ((uint32_t)__bfloat16_as_ushort(b) << 16) | (uint32_t)__bfloat16_as_ushort(a);
}

// ---------------- fused zero + dtype detect ----------------
__global__ void zero_detect_kernel(const int* __restrict__ ei1_i32) {
    int i = blockIdx.x * 256 + threadIdx.x;
    if (i < T2_SLOT) d_T2g[i] = 0.0f;          // GEMM accum target (slot 0)
    if (i < N1v) { d_deg1[i] = 0.0f; d_cnt1[i] = 0; d_fill1[i] = 0; }
    if (i < N2v) { d_deg2[i] = 0.0f; d_cnt2[i] = 0; d_fill2[i] = 0; }
    if (i < Bv * Cv) d_logits[i] = 0.0f;
    if (i == 0) {
        int is64 = 1;
        for (int j = 1; j < 64; j += 2)
            if (ei1_i32[j] != 0) { is64 = 0; break; }
        d_is64 = is64;
    }
}

// ---------------- b_map -> bf16 hi/lo (one pass, HBM-bound) ----------------
__global__ void aconv_kernel(const float* __restrict__ A) {
    long long i = ((long long)blockIdx.x * 256 + threadIdx.x) * 4;
    float4 v = __ldg((const float4*)(A + i));
    __nv_bfloat16 h0 = __float2bfloat16(v.x);
    __nv_bfloat16 h1 = __float2bfloat16(v.y);
    __nv_bfloat16 h2 = __float2bfloat16(v.z);
    __nv_bfloat16 h3 = __float2bfloat16(v.w);
    __nv_bfloat16 l0 = __float2bfloat16(v.x - __bfloat162float(h0));
    __nv_bfloat16 l1 = __float2bfloat16(v.y - __bfloat162float(h1));
    __nv_bfloat16 l2 = __float2bfloat16(v.z - __bfloat162float(h2));
    __nv_bfloat16 l3 = __float2bfloat16(v.w - __bfloat162float(h3));
    *(uint2*)((char*)d_A_hi + i * 2) = make_uint2(pack_bf2(h0, h1), pack_bf2(h2, h3));
    *(uint2*)((char*)d_A_lo + i * 2) = make_uint2(pack_bf2(l0, l1), pack_bf2(l2, l3));
}

// ---------------- fused degree kernel ----------------
__global__ void deg12_kernel(const void* __restrict__ ei1, const float* __restrict__ w1,
                             const void* __restrict__ ei2, const float* __restrict__ w2) {
    int i = blockIdx.x * 256 + threadIdx.x;
    int is64 = d_is64;
    if (i < E1v) {
        int d = load_idx(ei1, E1v + i, is64);
        if ((unsigned)d < N1v) { atomicAdd(&d_deg1[d], w1[i]); atomicAdd(&d_cnt1[d], 1); }
    } else if (i < E1v + E2v) {
        int e = i - E1v;
        int d = load_idx(ei2, E2v + e, is64);
        if ((unsigned)d < N2v) { atomicAdd(&d_deg2[d], w2[e]); atomicAdd(&d_cnt2[d], 1); }
    }
}

// single block: dinv + exclusive scans of cnt -> row
__global__ void scan_kernel() {
    __shared__ int sh[1024];
    int tid = threadIdx.x;
#pragma unroll
    for (int j = 0; j < 8; j++) {
        int i = tid * 8 + j;
        float v = d_deg1[i];
        d_dinv1[i] = (v > 0.0f) ? rsqrtf(v) : 0.0f;
    }
#pragma unroll
    for (int j = 0; j < 4; j++) {
        int i = tid * 4 + j;
        float v = d_deg2[i];
        d_dinv2[i] = (v > 0.0f) ? rsqrtf(v) : 0.0f;
    }
    {
        int v[8]; int s = 0;
#pragma unroll
        for (int j = 0; j < 8; j++) { v[j] = d_cnt1[tid * 8 + j]; s += v[j]; }
        sh[tid] = s; __syncthreads();
        for (int off = 1; off < 1024; off <<= 1) {
            int x = (tid >= off) ? sh[tid - off] : 0;
            __syncthreads();
            sh[tid] += x;
            __syncthreads();
        }
        int run = sh[tid] - s;
#pragma unroll
        for (int j = 0; j < 8; j++) { d_row1[tid * 8 + j] = run; run += v[j]; }
        if (tid == 1023) d_row1[N1v] = run;
    }
    __syncthreads();
    {
        int v[4]; int s = 0;
#pragma unroll
        for (int j = 0; j < 4; j++) { v[j] = d_cnt2[tid * 4 + j]; s += v[j]; }
        sh[tid] = s; __syncthreads();
        for (int off = 1; off < 1024; off <<= 1) {
            int x = (tid >= off) ? sh[tid - off] : 0;
            __syncthreads();
            sh[tid] += x;
            __syncthreads();
        }
        int run = sh[tid] - s;
#pragma unroll
        for (int j = 0; j < 4; j++) { d_row2[tid * 4 + j] = run; run += v[j]; }
        if (tid == 1023) d_row2[N2v] = run;
    }
}

__global__ void fill12_kernel(const void* __restrict__ ei1, const float* __restrict__ w1,
                              const void* __restrict__ ei2, const float* __restrict__ w2) {
    int i = blockIdx.x * 256 + threadIdx.x;
    int is64 = d_is64;
    if (i < E1v) {
        int s = load_idx(ei1, i, is64);
        int d = load_idx(ei1, E1v + i, is64);
        if ((unsigned)s < N1v && (unsigned)d < N1v) {
            float v = -w1[i] * d_dinv1[s] * d_dinv1[d];
            int p = d_row1[d] + atomicAdd(&d_fill1[d], 1);
            if ((unsigned)p < E1v) { d_csrc1[p] = s; d_cval1[p] = v; }
        }
    } else if (i < E1v + E2v) {
        int e = i - E1v;
        int s = load_idx(ei2, e, is64);
        int d = load_idx(ei2, E2v + e, is64);
        if ((unsigned)s < N2v && (unsigned)d < N2v) {
            float v = -w2[e] * d_dinv2[s] * d_dinv2[d];
            int p = d_row2[d] + atomicAdd(&d_fill2[d], 1);
            if ((unsigned)p < E2v) { d_csrc2[p] = s; d_cval2[p] = v; }
        }
    }
}

// ---------------- persistent prop1: transpose + 11 Chebyshev props, ONE launch ----------------
// 512 blocks x 256 threads (all resident). thread <-> (n, j): float4 over comps j*4..j*4+3.
__global__ void __launch_bounds__(256, 4) prop1_all(const float* __restrict__ x) {
    int gt = blockIdx.x * 256 + threadIdx.x;   // 0..131071
    int n = gt >> 4, j = gt & 15;
    bool act = (j < 15);
    float4 pv1 = make_float4(0.f, 0.f, 0.f, 0.f);
    float4 pv2 = make_float4(0.f, 0.f, 0.f, 0.f);
    // k = 0 : T0 = x transposed ; comp c = t*4 + b with t=j
    if (act) {
        float4 v;
        v.x = __ldg(&x[0 * (N1v * Tv) + n * Tv + j]);
        v.y = __ldg(&x[1 * (N1v * Tv) + n * Tv + j]);
        v.z = __ldg(&x[2 * (N1v * Tv) + n * Tv + j]);
        v.w = __ldg(&x[3 * (N1v * Tv) + n * Tv + j]);
        *(float4*)&d_T1[n * D1v + j * 4] = v;
        pv1 = v;
    }
    for (int k = 1; k < Kv; k++) {
        grid_barrier(0);
        if (act) {
            const float* __restrict__ prev = d_T1 + (k - 1) * T1_SLOT;
            int beg = d_row1[n], end = d_row1[n + 1];
            float4 acc = make_float4(0.f, 0.f, 0.f, 0.f);
            for (int e = beg; e < end; e++) {
                float w = d_cval1[e];
                float4 s = *(const float4*)&prev[d_csrc1[e] * D1v + j * 4];
                acc.x += w * s.x; acc.y += w * s.y; acc.z += w * s.z; acc.w += w * s.w;
            }
            float4 v;
            if (k == 1) v = acc;
            else {
                v.x = 2.0f * acc.x - pv2.x; v.y = 2.0f * acc.y - pv2.y;
                v.z = 2.0f * acc.z - pv2.z; v.w = 2.0f * acc.w - pv2.w;
            }
            pv2 = pv1; pv1 = v;
            *(float4*)&d_T1[k * T1_SLOT + n * D1v + j * 4] = v;
        }
    }
}

// ---------------- persistent prop2: 11 Chebyshev props, ONE launch ----------------
// 512 blocks x 256 threads. thread <-> (n, j) handling b in {b0, b0+2}; float4 over d.
__global__ void __launch_bounds__(256, 4) prop2_all() {
    int gt = blockIdx.x * 256 + threadIdx.x;   // 0..131071
    int n = gt >> 5;
    int r = gt & 31;
    int b0 = r >> 4;        // 0 or 1
    int j  = r & 15;        // 0..15
    float4 pv1[2], pv2[2];
#pragma unroll
    for (int i = 0; i < 2; i++) {
        int b = b0 + 2 * i;
        pv1[i] = *(const float4*)&d_T2g[b * T2_BOFF + n * 64 + j * 4];   // slot 0 = h2
        pv2[i] = make_float4(0.f, 0.f, 0.f, 0.f);
    }
    for (int k = 1; k < Kv; k++) {
        if (k >= 2) grid_barrier(1);    // k=1 reads slot0 (written by prior launch)
        int beg = d_row2[n], end = d_row2[n + 1];
#pragma unroll
        for (int i = 0; i < 2; i++) {
            int b = b0 + 2 * i;
            const float* __restrict__ prev = d_T2g + (k - 1) * T2_SLOT + b * T2_BOFF;
            float4 acc = make_float4(0.f, 0.f, 0.f, 0.f);
            for (int e = beg; e < end; e++) {
                float w = d_cval2[e];
                float4 s = *(const float4*)&prev[d_csrc2[e] * 64 + j * 4];
                acc.x += w * s.x; acc.y += w * s.y; acc.z += w * s.z; acc.w += w * s.w;
            }
            float4 v;
            if (k == 1) v = acc;
            else {
                v.x = 2.0f * acc.x - pv2[i].x; v.y = 2.0f * acc.y - pv2[i].y;
                v.z = 2.0f * acc.z - pv2[i].z; v.w = 2.0f * acc.w - pv2[i].w;
            }
            pv2[i] = pv1[i]; pv1[i] = v;
            *(float4*)&d_T2g[k * T2_SLOT + b * T2_BOFF + n * 64 + j * 4] = v;
        }
    }
}

// ---------------- einsum 1 (256-thread blocks) ----------------
__global__ void einsum1_kernel(const float* __restrict__ W1, const float* __restrict__ b1) {
    __shared__ __align__(16) float sW[Kv * Tv * G1v];
    for (int i = threadIdx.x; i < Kv * Tv * G1v; i += 256) sW[i] = W1[i];
    __syncthreads();
    int t = blockIdx.x * 256 + threadIdx.x;
    int n = t >> 2, b = t & 3;
    float4 acc[16];
#pragma unroll
    for (int q = 0; q < 16; q++) acc[q] = make_float4(0.f, 0.f, 0.f, 0.f);
    for (int k = 0; k < Kv; k++) {
        const float* tp = d_T1 + k * T1_SLOT + n * D1v + b;
        const float* wp = sW + k * (Tv * G1v);
        for (int d = 0; d < Tv; d++) {
            float tv = __ldg(&tp[d * 4]);
            const float4* w4 = (const float4*)(wp + d * G1v);
#pragma unroll
            for (int q = 0; q < 16; q++) {
                float4 w = w4[q];
                acc[q].x += tv * w.x; acc[q].y += tv * w.y;
                acc[q].z += tv * w.z; acc[q].w += tv * w.w;
            }
        }
    }
    float* yp = d_y1 + n * 256 + b;
#pragma unroll
    for (int q = 0; q < 16; q++) {
        int g0 = q * 4;
        yp[(g0 + 0) * 4] = fmaxf(acc[q].x + b1[g0 + 0], 0.0f);
        yp[(g0 + 1) * 4] = fmaxf(acc[q].y + b1[g0 + 1], 0.0f);
        yp[(g0 + 2) * 4] = fmaxf(acc[q].z + b1[g0 + 2], 0.0f);
        yp[(g0 + 3) * 4] = fmaxf(acc[q].w + b1[g0 + 3], 0.0f);
    }
}

// ---------------- y1 -> transposed bf16 hi/lo split ----------------
__global__ void y1split_kernel() {
    __shared__ float tile[32][33];
    int k0 = blockIdx.x * 32, c0 = blockIdx.y * 32;
    int tx = threadIdx.x, ty = threadIdx.y;   // 32 x 8
#pragma unroll
    for (int i = 0; i < 4; i++)
        tile[ty + 8 * i][tx] = d_y1[(k0 + ty + 8 * i) * 256 + c0 + tx];
    __syncthreads();
#pragma unroll
    for (int i = 0; i < 4; i++) {
        int c = c0 + ty + 8 * i;
        float v = tile[tx][ty + 8 * i];
        __nv_bfloat16 h = __float2bfloat16(v);
        float lo = v - __bfloat162float(h);
        long long idx = (long long)c * N1v + k0 + tx;
        d_y1t_hi[idx] = __bfloat16_as_ushort(h);
        d_y1t_lo[idx] = __bfloat16_as_ushort(__float2bfloat16(lo));
    }
}

// ---------------- warp-MMA pooling GEMM (cp.async 3-stage pipeline) ----------------
#define KSPLIT 2
#define KB2 64
#define ASTRIDE 72
#define MAT_BYTES (128 * ASTRIDE * 2)
#define STG_BYTES (4 * MAT_BYTES)
#define NSTAGE 3
#define SMEM_GEMM_TOTAL (NSTAGE * STG_BYTES)   // 221184

__device__ __forceinline__ void fill_async(uint32_t sbase, int s, int m0, int n0, int kblk) {
    int t = threadIdx.x;
    uint32_t ah = sbase + s * STG_BYTES;
    uint32_t al = ah + MAT_BYTES;
    uint32_t bh = al + MAT_BYTES;
    uint32_t bl = bh + MAT_BYTES;
#pragma unroll
    for (int i = 0; i < 4; i++) {
        int idx = t + 256 * i;
        int r = idx >> 3, c = (idx & 7) * 8;
        uint32_t so = (uint32_t)(r * ASTRIDE + c) * 2;
        long long ka = ((long long)(m0 + r) * N1v + kblk + c) * 2;
        cp16(ah + so, (const char*)d_A_hi + ka);
        cp16(al + so, (const char*)d_A_lo + ka);
        long long kb = ((long long)(n0 + r) * N1v + kblk + c) * 2;
        cp16(bh + so, (const char*)d_y1t_hi + kb);
        cp16(bl + so, (const char*)d_y1t_lo + kb);
    }
}

__global__ void __launch_bounds__(256, 1) pool_gemm_mma() {
    extern __shared__ __align__(16) char smem[];
    uint32_t sbase = smem_to_u32(smem);
    int tid = threadIdx.x, wid = tid >> 5, lid = tid & 31;
    int m0 = blockIdx.y * 128, n0 = blockIdx.z * 128;
    int kbase = blockIdx.x * (N1v / KSPLIT);
    const int NB = (N1v / KSPLIT) / KB2;      // 64
    int wm = (wid >> 1) * 32;
    int wn = (wid & 1) * 64;

    float acc[2][8][4];
#pragma unroll
    for (int mt = 0; mt < 2; mt++)
#pragma unroll
        for (int nt = 0; nt < 8; nt++)
#pragma unroll
            for (int q = 0; q < 4; q++) acc[mt][nt][q] = 0.0f;

    int arow = wm + (lid & 15);
    int acol = (lid >> 4) * 8;
    int l16 = lid & 15;
    int brow = wn + (l16 & 7);
    int bcol = ((l16 >> 3) & 1) * 8;

    fill_async(sbase, 0, m0, n0, kbase);            CP_COMMIT();
    fill_async(sbase, 1, m0, n0, kbase + KB2);      CP_COMMIT();
    fill_async(sbase, 2, m0, n0, kbase + 2 * KB2);  CP_COMMIT();

    for (int it = 0; it < NB; it++) {
        CP_WAIT2();
        __syncthreads();
        int s = it % NSTAGE;
        uint32_t aHiB = sbase + s * STG_BYTES;
        uint32_t aLoB = aHiB + MAT_BYTES;
        uint32_t bHiB = aLoB + MAT_BYTES;
        uint32_t bLoB = bHiB + MAT_BYTES;
#pragma unroll
        for (int k16 = 0; k16 < KB2 / 16; k16++) {
            uint32_t ah[2][4], alo[2][4], bhf[8][2], blf[8][2];
#pragma unroll
            for (int mt = 0; mt < 2; mt++) {
                uint32_t off = (uint32_t)(((arow + mt * 16) * ASTRIDE + k16 * 16 + acol) * 2);
                ldsm_x4(ah[mt],  aHiB + off);
                ldsm_x4(alo[mt], aLoB + off);
            }
#pragma unroll
            for (int nt = 0; nt < 8; nt++) {
                uint32_t off = (uint32_t)(((brow + nt * 8) * ASTRIDE + k16 * 16 + bcol) * 2);
                ldsm_x2(bhf[nt], bHiB + off);
                ldsm_x2(blf[nt], bLoB + off);
            }
#pragma unroll
            for (int mt = 0; mt < 2; mt++)
#pragma unroll
                for (int nt = 0; nt < 8; nt++) {
                    mma_bf16(acc[mt][nt], ah[mt],  bhf[nt]);
                    mma_bf16(acc[mt][nt], alo[mt], bhf[nt]);
                    mma_bf16(acc[mt][nt], ah[mt],  blf[nt]);
                }
        }
        __syncthreads();
        if (it + NSTAGE < NB)
            fill_async(sbase, s, m0, n0, kbase + (it + NSTAGE) * KB2);
        CP_COMMIT();
    }

    // epilogue: atomic-accumulate into d_T2g slot 0 ([b][m][g], col = g*4+b)
#pragma unroll
    for (int mt = 0; mt < 2; mt++) {
        int m_lo = m0 + wm + mt * 16 + (lid >> 2);
        int m_hi = m_lo + 8;
#pragma unroll
        for (int nt = 0; nt < 8; nt++) {
            int c0 = n0 + wn + nt * 8 + (lid & 3) * 2;
            int c1 = c0 + 1;
            atomicAdd(&d_T2g[(c0 & 3) * T2_BOFF + m_lo * 64 + (c0 >> 2)], acc[mt][nt][0]);
            atomicAdd(&d_T2g[(c1 & 3) * T2_BOFF + m_lo * 64 + (c1 >> 2)], acc[mt][nt][1]);
            atomicAdd(&d_T2g[(c0 & 3) * T2_BOFF + m_hi * 64 + (c0 >> 2)], acc[mt][nt][2]);
            atomicAdd(&d_T2g[(c1 & 3) * T2_BOFF + m_hi * 64 + (c1 >> 2)], acc[mt][nt][3]);
        }
    }
}

// ---------------- einsum 2 (128-thread blocks) ----------------
__global__ void einsum2_kernel(const float* __restrict__ W2, const float* __restrict__ b2) {
    __shared__ __align__(16) float sW[64 * 32];
    int t = blockIdx.x * 128 + threadIdx.x;
    int n = t >> 2, b = t & 3;
    float4 acc[8];
#pragma unroll
    for (int q = 0; q < 8; q++) acc[q] = make_float4(0.f, 0.f, 0.f, 0.f);
    for (int k = 0; k < Kv; k++) {
        __syncthreads();
        for (int i = threadIdx.x; i < 2048; i += 128) sW[i] = W2[k * 2048 + i];
        __syncthreads();
        const float* tp = d_T2g + k * T2_SLOT + b * T2_BOFF + n * 64;
        for (int d = 0; d < 64; d++) {
            float tv = __ldg(&tp[d]);
            const float4* w4 = (const float4*)(sW + d * 32);
#pragma unroll
            for (int q = 0; q < 8; q++) {
                float4 w = w4[q];
                acc[q].x += tv * w.x; acc[q].y += tv * w.y;
                acc[q].z += tv * w.z; acc[q].w += tv * w.w;
            }
        }
    }
    float* yp = d_y2 + n * 128 + b;
#pragma unroll
    for (int q = 0; q < 8; q++) {
        int g0 = q * 4;
        yp[(g0 + 0) * 4] = acc[q].x + b2[g0 + 0];
        yp[(g0 + 1) * 4] = acc[q].y + b2[g0 + 1];
        yp[(g0 + 2) * 4] = acc[q].z + b2[g0 + 2];
        yp[(g0 + 3) * 4] = acc[q].w + b2[g0 + 3];
    }
}

// ---------------- FC (split-K) + log_softmax ----------------
__global__ void fc_kernel(const float* __restrict__ fcw) {
    int bc = blockIdx.x;
    int b = bc / 6, c = bc - b * 6;
    int ks = blockIdx.y;
    const float4* w4 = (const float4*)(fcw + (long long)c * 131072);
    const float4* h4 = (const float4*)(d_y2 + b * 131072);
    float s = 0.0f;
    int beg = ks * 4096, end = beg + 4096;
    for (int i = beg + threadIdx.x; i < end; i += 256) {
        float4 a = __ldg(&w4[i]);
        float4 h = h4[i];
        s += a.x * h.x + a.y * h.y + a.z * h.z + a.w * h.w;
    }
    __shared__ float sh[256];
    sh[threadIdx.x] = s;
    __syncthreads();
    for (int off = 128; off > 0; off >>= 1) {
        if (threadIdx.x < off) sh[threadIdx.x] += sh[threadIdx.x + off];
        __syncthreads();
    }
    if (threadIdx.x == 0) atomicAdd(&d_logits[bc], sh[0]);
}

__global__ void lsm_kernel(float* __restrict__ out, const float* __restrict__ fcb) {
    int b = threadIdx.x;
    if (b < Bv) {
        float l[Cv];
        float m = -1e30f;
#pragma unroll
        for (int c = 0; c < Cv; c++) { l[c] = d_logits[b * Cv + c] + fcb[c]; m = fmaxf(m, l[c]); }
        float s = 0.0f;
#pragma unroll
        for (int c = 0; c < Cv; c++) s += expf(l[c] - m);
        float L = logf(s);
#pragma unroll
        for (int c = 0; c < Cv; c++) out[b * Cv + c] = l[c] - m - L;
    }
}

// ---------------- launch ----------------
extern "C" void kernel_launch(void* const* d_in, const int* in_sizes, int n_in,
                              void* d_out, int out_size) {
    const float* x    = (const float*)d_in[0];
    const void*  ei1  = d_in[1];
    const float* ew1  = (const float*)d_in[2];
    const void*  ei2  = d_in[3];
    const float* ew2  = (const float*)d_in[4];
    const float* bmap = (const float*)d_in[5];
    const float* W1   = (const float*)d_in[6];
    const float* b1   = (const float*)d_in[7];
    const float* W2   = (const float*)d_in[8];
    const float* b2   = (const float*)d_in[9];
    const float* fcw  = (const float*)d_in[10];
    const float* fcb  = (const float*)d_in[11];
    float* out = (float*)d_out;

    cudaFuncSetAttribute(pool_gemm_mma, cudaFuncAttributeMaxDynamicSharedMemorySize,
                         SMEM_GEMM_TOTAL);

    zero_detect_kernel<<<T2_SLOT / 256, 256>>>((const int*)ei1);
    aconv_kernel<<<32768, 256>>>(bmap);
    deg12_kernel<<<(E1v + E2v) / 256, 256>>>(ei1, ew1, ei2, ew2);
    scan_kernel<<<1, 1024>>>();
    fill12_kernel<<<(E1v + E2v) / 256, 256>>>(ei1, ew1, ei2, ew2);

    prop1_all<<<512, 256>>>(x);
    einsum1_kernel<<<(N1v * Bv) / 256, 256>>>(W1, b1);

    y1split_kernel<<<dim3(N1v / 32, 256 / 32), dim3(32, 8)>>>();
    pool_gemm_mma<<<dim3(KSPLIT, 32, 2), 256, SMEM_GEMM_TOTAL>>>();

    prop2_all<<<512, 256>>>();
    einsum2_kernel<<<(N2v * Bv) / 128, 128>>>(W2, b2);

    fc_kernel<<<dim3(Bv * Cv, 8), 256>>>(fcw);
    lsm_kernel<<<1, 32>>>(out, fcb);
}

// round 17
// speedup vs baseline: 1.2390x; 1.0191x over previous
#include <cuda_runtime.h>
#include <cuda_bf16.h>
#include <cstdint>

// ---------------- problem constants ----------------
#define N1v 8192
#define N2v 4096
#define Tv 15
#define Bv 4
#define E1v 131072
#define E2v 65536
#define Kv 12
#define G1v 64
#define G2v 32
#define Cv 6

#define D1v 60                    // T*B comps per node, layer1 (layout t*4+b)
#define T1_SLOT (N1v * D1v)       // 491520
#define T2_SLOT (N2v * 64 * Bv)   // 1048576, layout [b][n][g]
#define T2_BOFF (N2v * 64)        // 262144

// ---------------- scratch (device globals; allocation-free) ----------------
__device__ int   d_is64;
__device__ float d_deg1[N1v];
__device__ float d_dinv1[N1v];
__device__ float d_deg2[N2v];
__device__ float d_dinv2[N2v];
__device__ int   d_cnt1[N1v];
__device__ int   d_fill1[N1v];
__device__ int   d_row1[N1v + 1];
__device__ int   d_cnt2[N2v];
__device__ int   d_fill2[N2v];
__device__ int   d_row2[N2v + 1];
__device__ int   d_csrc1[E1v];
__device__ float d_cval1[E1v];
__device__ int   d_csrc2[E2v];
__device__ float d_cval2[E2v];
__device__ float d_T1[Kv * T1_SLOT];    // Cheb tensors layer1, [k][n*60 + t*4 + b]
__device__ float d_y1[N1v * 256];       // relu(conv1), [n*256 + g*4 + b]
__device__ unsigned short d_y1t_hi[256 * N1v];   // y1^T hi bf16, [col][k]
__device__ unsigned short d_y1t_lo[256 * N1v];   // y1^T lo bf16, [col][k]
__device__ unsigned short d_A_hi[(long long)N2v * N1v];   // b_map hi bf16
__device__ unsigned short d_A_lo[(long long)N2v * N1v];   // b_map lo bf16
__device__ float d_T2g[Kv * T2_SLOT];   // Cheb tensors layer2, [k][b][n][g]
__device__ float d_y2[N2v * 128];       // conv2 out, [n*128 + g*4 + b] (== torch flat order)
__device__ float d_logits[Bv * Cv];
__device__ unsigned int g_bcount[2];
__device__ volatile unsigned int g_bgen[2];

// ================= helpers =================
__device__ __forceinline__ uint32_t smem_to_u32(const void* smem_ptr) {
    uint32_t addr;
    asm("{ .reg .u64 tmp; cvta.to.shared.u64 tmp, %1; cvt.u32.u64 %0, tmp; }"
        : "=r"(addr) : "l"(smem_ptr));
    return addr;
}
__device__ __forceinline__ void ldsm_x4(uint32_t* r, uint32_t addr) {
    asm volatile("ldmatrix.sync.aligned.m8n8.x4.shared.b16 {%0,%1,%2,%3}, [%4];"
        : "=r"(r[0]), "=r"(r[1]), "=r"(r[2]), "=r"(r[3]) : "r"(addr));
}
__device__ __forceinline__ void mma_bf16(float* c, const uint32_t* a, const uint32_t* b) {
    asm volatile(
        "mma.sync.aligned.m16n8k16.row.col.f32.bf16.bf16.f32 "
        "{%0,%1,%2,%3}, {%4,%5,%6,%7}, {%8,%9}, {%0,%1,%2,%3};"
        : "+f"(c[0]), "+f"(c[1]), "+f"(c[2]), "+f"(c[3])
        : "r"(a[0]), "r"(a[1]), "r"(a[2]), "r"(a[3]), "r"(b[0]), "r"(b[1]));
}
__device__ __forceinline__ void cp16(uint32_t s, const void* g) {
    asm volatile("cp.async.cg.shared.global [%0], [%1], 16;" :: "r"(s), "l"(g) : "memory");
}
#define CP_COMMIT() asm volatile("cp.async.commit_group;" ::: "memory")
#define CP_WAIT1()  asm volatile("cp.async.wait_group 1;" ::: "memory")

__device__ __forceinline__ void grid_barrier(int id) {
    __syncthreads();
    if (threadIdx.x == 0) {
        __threadfence();
        unsigned int gen = g_bgen[id];
        if (atomicAdd(&g_bcount[id], 1u) == gridDim.x - 1) {
            g_bcount[id] = 0;
            __threadfence();
            g_bgen[id] = gen + 1;
        } else {
            while (g_bgen[id] == gen) { __nanosleep(64); }
        }
        __threadfence();
    }
    __syncthreads();
}

__device__ __forceinline__ int load_idx(const void* ei, int pos, int is64) {
    if (is64) return (int)((const long long*)ei)[pos];
    return ((const int*)ei)[pos];
}
__device__ __forceinline__ uint32_t pack_bf2(__nv_bfloat16 a, __nv_bfloat16 b) {
    return ((uint32_t)__bfloat16_as_ushort(b) << 16) | (uint32_t)__bfloat16_as_ushort(a);
}

// ---------------- fused zero + dtype detect ----------------
__global__ void zero_detect_kernel(const int* __restrict__ ei1_i32) {
    int i = blockIdx.x * 256 + threadIdx.x;
    if (i < T2_SLOT) d_T2g[i] = 0.0f;          // GEMM accum target (slot 0)
    if (i < N1v) { d_deg1[i] = 0.0f; d_cnt1[i] = 0; d_fill1[i] = 0; }
    if (i < N2v) { d_deg2[i] = 0.0f; d_cnt2[i] = 0; d_fill2[i] = 0; }
    if (i < Bv * Cv) d_logits[i] = 0.0f;
    if (i == 0) {
        int is64 = 1;
        for (int j = 1; j < 64; j += 2)
            if (ei1_i32[j] != 0) { is64 = 0; break; }
        d_is64 = is64;
    }
}

// ---------------- b_map -> bf16 hi/lo (one pass, HBM-bound) ----------------
__global__ void aconv_kernel(const float* __restrict__ A) {
    long long i = ((long long)blockIdx.x * 256 + threadIdx.x) * 4;
    float4 v = __ldg((const float4*)(A + i));
    __nv_bfloat16 h0 = __float2bfloat16(v.x);
    __nv_bfloat16 h1 = __float2bfloat16(v.y);
    __nv_bfloat16 h2 = __float2bfloat16(v.z);
    __nv_bfloat16 h3 = __float2bfloat16(v.w);
    __nv_bfloat16 l0 = __float2bfloat16(v.x - __bfloat162float(h0));
    __nv_bfloat16 l1 = __float2bfloat16(v.y - __bfloat162float(h1));
    __nv_bfloat16 l2 = __float2bfloat16(v.z - __bfloat162float(h2));
    __nv_bfloat16 l3 = __float2bfloat16(v.w - __bfloat162float(h3));
    *(uint2*)((char*)d_A_hi + i * 2) = make_uint2(pack_bf2(h0, h1), pack_bf2(h2, h3));
    *(uint2*)((char*)d_A_lo + i * 2) = make_uint2(pack_bf2(l0, l1), pack_bf2(l2, l3));
}

// ---------------- fused degree kernel ----------------
__global__ void deg12_kernel(const void* __restrict__ ei1, const float* __restrict__ w1,
                             const void* __restrict__ ei2, const float* __restrict__ w2) {
    int i = blockIdx.x * 256 + threadIdx.x;
    int is64 = d_is64;
    if (i < E1v) {
        int d = load_idx(ei1, E1v + i, is64);
        if ((unsigned)d < N1v) { atomicAdd(&d_deg1[d], w1[i]); atomicAdd(&d_cnt1[d], 1); }
    } else if (i < E1v + E2v) {
        int e = i - E1v;
        int d = load_idx(ei2, E2v + e, is64);
        if ((unsigned)d < N2v) { atomicAdd(&d_deg2[d], w2[e]); atomicAdd(&d_cnt2[d], 1); }
    }
}

// single block: dinv + warp-shuffle exclusive scans of cnt -> row
__global__ void scan_kernel() {
    __shared__ int wsum[32];
    int tid = threadIdx.x, lane = tid & 31, warp = tid >> 5;
#pragma unroll
    for (int j = 0; j < 8; j++) {
        int i = tid * 8 + j;
        float v = d_deg1[i];
        d_dinv1[i] = (v > 0.0f) ? rsqrtf(v) : 0.0f;
    }
#pragma unroll
    for (int j = 0; j < 4; j++) {
        int i = tid * 4 + j;
        float v = d_deg2[i];
        d_dinv2[i] = (v > 0.0f) ? rsqrtf(v) : 0.0f;
    }
    {
        int v[8]; int s = 0;
#pragma unroll
        for (int j = 0; j < 8; j++) { v[j] = d_cnt1[tid * 8 + j]; s += v[j]; }
        int ps = s;
#pragma unroll
        for (int off = 1; off < 32; off <<= 1) {
            int t = __shfl_up_sync(0xffffffffu, ps, off);
            if (lane >= off) ps += t;
        }
        if (lane == 31) wsum[warp] = ps;
        __syncthreads();
        if (warp == 0) {
            int ws = wsum[lane];
#pragma unroll
            for (int off = 1; off < 32; off <<= 1) {
                int t = __shfl_up_sync(0xffffffffu, ws, off);
                if (lane >= off) ws += t;
            }
            wsum[lane] = ws;
        }
        __syncthreads();
        int run = (warp ? wsum[warp - 1] : 0) + ps - s;
#pragma unroll
        for (int j = 0; j < 8; j++) { d_row1[tid * 8 + j] = run; run += v[j]; }
        if (tid == 1023) d_row1[N1v] = run;
    }
    __syncthreads();
    {
        int v[4]; int s = 0;
#pragma unroll
        for (int j = 0; j < 4; j++) { v[j] = d_cnt2[tid * 4 + j]; s += v[j]; }
        int ps = s;
#pragma unroll
        for (int off = 1; off < 32; off <<= 1) {
            int t = __shfl_up_sync(0xffffffffu, ps, off);
            if (lane >= off) ps += t;
        }
        if (lane == 31) wsum[warp] = ps;
        __syncthreads();
        if (warp == 0) {
            int ws = wsum[lane];
#pragma unroll
            for (int off = 1; off < 32; off <<= 1) {
                int t = __shfl_up_sync(0xffffffffu, ws, off);
                if (lane >= off) ws += t;
            }
            wsum[lane] = ws;
        }
        __syncthreads();
        int run = (warp ? wsum[warp - 1] : 0) + ps - s;
#pragma unroll
        for (int j = 0; j < 4; j++) { d_row2[tid * 4 + j] = run; run += v[j]; }
        if (tid == 1023) d_row2[N2v] = run;
    }
}

__global__ void fill12_kernel(const void* __restrict__ ei1, const float* __restrict__ w1,
                              const void* __restrict__ ei2, const float* __restrict__ w2) {
    int i = blockIdx.x * 256 + threadIdx.x;
    int is64 = d_is64;
    if (i < E1v) {
        int s = load_idx(ei1, i, is64);
        int d = load_idx(ei1, E1v + i, is64);
        if ((unsigned)s < N1v && (unsigned)d < N1v) {
            float v = -w1[i] * d_dinv1[s] * d_dinv1[d];
            int p = d_row1[d] + atomicAdd(&d_fill1[d], 1);
            if ((unsigned)p < E1v) { d_csrc1[p] = s; d_cval1[p] = v; }
        }
    } else if (i < E1v + E2v) {
        int e = i - E1v;
        int s = load_idx(ei2, e, is64);
        int d = load_idx(ei2, E2v + e, is64);
        if ((unsigned)s < N2v && (unsigned)d < N2v) {
            float v = -w2[e] * d_dinv2[s] * d_dinv2[d];
            int p = d_row2[d] + atomicAdd(&d_fill2[d], 1);
            if ((unsigned)p < E2v) { d_csrc2[p] = s; d_cval2[p] = v; }
        }
    }
}

// ---------------- persistent prop1: transpose + 11 Chebyshev props, ONE launch ----------------
__global__ void __launch_bounds__(256, 4) prop1_all(const float* __restrict__ x) {
    int gt = blockIdx.x * 256 + threadIdx.x;   // 0..131071
    int n = gt >> 4, j = gt & 15;
    bool act = (j < 15);
    float4 pv1 = make_float4(0.f, 0.f, 0.f, 0.f);
    float4 pv2 = make_float4(0.f, 0.f, 0.f, 0.f);
    if (act) {
        float4 v;
        v.x = __ldg(&x[0 * (N1v * Tv) + n * Tv + j]);
        v.y = __ldg(&x[1 * (N1v * Tv) + n * Tv + j]);
        v.z = __ldg(&x[2 * (N1v * Tv) + n * Tv + j]);
        v.w = __ldg(&x[3 * (N1v * Tv) + n * Tv + j]);
        *(float4*)&d_T1[n * D1v + j * 4] = v;
        pv1 = v;
    }
    for (int k = 1; k < Kv; k++) {
        grid_barrier(0);
        if (act) {
            const float* __restrict__ prev = d_T1 + (k - 1) * T1_SLOT;
            int beg = d_row1[n], end = d_row1[n + 1];
            float4 acc = make_float4(0.f, 0.f, 0.f, 0.f);
            for (int e = beg; e < end; e++) {
                float w = d_cval1[e];
                float4 s = *(const float4*)&prev[d_csrc1[e] * D1v + j * 4];
                acc.x += w * s.x; acc.y += w * s.y; acc.z += w * s.z; acc.w += w * s.w;
            }
            float4 v;
            if (k == 1) v = acc;
            else {
                v.x = 2.0f * acc.x - pv2.x; v.y = 2.0f * acc.y - pv2.y;
                v.z = 2.0f * acc.z - pv2.z; v.w = 2.0f * acc.w - pv2.w;
            }
            pv2 = pv1; pv1 = v;
            *(float4*)&d_T1[k * T1_SLOT + n * D1v + j * 4] = v;
        }
    }
}

// ---------------- persistent prop2: 11 Chebyshev props, ONE launch ----------------
__global__ void __launch_bounds__(256, 4) prop2_all() {
    int gt = blockIdx.x * 256 + threadIdx.x;   // 0..131071
    int n = gt >> 5;
    int r = gt & 31;
    int b0 = r >> 4;
    int j  = r & 15;
    float4 pv1[2], pv2[2];
#pragma unroll
    for (int i = 0; i < 2; i++) {
        int b = b0 + 2 * i;
        pv1[i] = *(const float4*)&d_T2g[b * T2_BOFF + n * 64 + j * 4];
        pv2[i] = make_float4(0.f, 0.f, 0.f, 0.f);
    }
    for (int k = 1; k < Kv; k++) {
        if (k >= 2) grid_barrier(1);
        int beg = d_row2[n], end = d_row2[n + 1];
#pragma unroll
        for (int i = 0; i < 2; i++) {
            int b = b0 + 2 * i;
            const float* __restrict__ prev = d_T2g + (k - 1) * T2_SLOT + b * T2_BOFF;
            float4 acc = make_float4(0.f, 0.f, 0.f, 0.f);
            for (int e = beg; e < end; e++) {
                float w = d_cval2[e];
                float4 s = *(const float4*)&prev[d_csrc2[e] * 64 + j * 4];
                acc.x += w * s.x; acc.y += w * s.y; acc.z += w * s.z; acc.w += w * s.w;
            }
            float4 v;
            if (k == 1) v = acc;
            else {
                v.x = 2.0f * acc.x - pv2[i].x; v.y = 2.0f * acc.y - pv2[i].y;
                v.z = 2.0f * acc.z - pv2[i].z; v.w = 2.0f * acc.w - pv2[i].w;
            }
            pv2[i] = pv1[i]; pv1[i] = v;
            *(float4*)&d_T2g[k * T2_SLOT + b * T2_BOFF + n * 64 + j * 4] = v;
        }
    }
}

// ---------------- einsum 1 ----------------
__global__ void einsum1_kernel(const float* __restrict__ W1, const float* __restrict__ b1) {
    __shared__ __align__(16) float sW[Kv * Tv * G1v];
    for (int i = threadIdx.x; i < Kv * Tv * G1v; i += 256) sW[i] = W1[i];
    __syncthreads();
    int t = blockIdx.x * 256 + threadIdx.x;
    int n = t >> 2, b = t & 3;
    float4 acc[16];
#pragma unroll
    for (int q = 0; q < 16; q++) acc[q] = make_float4(0.f, 0.f, 0.f, 0.f);
    for (int k = 0; k < Kv; k++) {
        const float* tp = d_T1 + k * T1_SLOT + n * D1v + b;
        const float* wp = sW + k * (Tv * G1v);
        for (int d = 0; d < Tv; d++) {
            float tv = __ldg(&tp[d * 4]);
            const float4* w4 = (const float4*)(wp + d * G1v);
#pragma unroll
            for (int q = 0; q < 16; q++) {
                float4 w = w4[q];
                acc[q].x += tv * w.x; acc[q].y += tv * w.y;
                acc[q].z += tv * w.z; acc[q].w += tv * w.w;
            }
        }
    }
    float* yp = d_y1 + n * 256 + b;
#pragma unroll
    for (int q = 0; q < 16; q++) {
        int g0 = q * 4;
        yp[(g0 + 0) * 4] = fmaxf(acc[q].x + b1[g0 + 0], 0.0f);
        yp[(g0 + 1) * 4] = fmaxf(acc[q].y + b1[g0 + 1], 0.0f);
        yp[(g0 + 2) * 4] = fmaxf(acc[q].z + b1[g0 + 2], 0.0f);
        yp[(g0 + 3) * 4] = fmaxf(acc[q].w + b1[g0 + 3], 0.0f);
    }
}

// ---------------- y1 -> transposed bf16 hi/lo split ----------------
__global__ void y1split_kernel() {
    __shared__ float tile[32][33];
    int k0 = blockIdx.x * 32, c0 = blockIdx.y * 32;
    int tx = threadIdx.x, ty = threadIdx.y;   // 32 x 8
#pragma unroll
    for (int i = 0; i < 4; i++)
        tile[ty + 8 * i][tx] = d_y1[(k0 + ty + 8 * i) * 256 + c0 + tx];
    __syncthreads();
#pragma unroll
    for (int i = 0; i < 4; i++) {
        int c = c0 + ty + 8 * i;
        float v = tile[tx][ty + 8 * i];
        __nv_bfloat16 h = __float2bfloat16(v);
        float lo = v - __bfloat162float(h);
        long long idx = (long long)c * N1v + k0 + tx;
        d_y1t_hi[idx] = __bfloat16_as_ushort(h);
        d_y1t_lo[idx] = __bfloat16_as_ushort(__float2bfloat16(lo));
    }
}

// ---------------- warp-MMA pooling GEMM: 512 threads, CTA tile 128x256, 2 stages ----------------
#define KSPLIT 4
#define KB2 64
#define ASTRIDE 72
#define A_MATB (128 * ASTRIDE * 2)   // 18432
#define B_MATB (256 * ASTRIDE * 2)   // 36864
#define STG2 (2 * A_MATB + 2 * B_MATB)   // 110592
#define OFF_AH 0
#define OFF_AL A_MATB
#define OFF_BH (2 * A_MATB)
#define OFF_BL (2 * A_MATB + B_MATB)
#define SMEM_GEMM_TOTAL (2 * STG2)   // 221184

__device__ __forceinline__ void fill_async(uint32_t sbase, int s, int m0, int kblk) {
    int t = threadIdx.x;
    uint32_t base = sbase + s * STG2;
    // A hi/lo: 128 rows x 8 chunks = 1024 each
#pragma unroll
    for (int i = 0; i < 2; i++) {
        int idx = t + 512 * i;
        int r = idx >> 3, c = (idx & 7) * 8;
        uint32_t so = (uint32_t)(r * ASTRIDE + c) * 2;
        long long ka = ((long long)(m0 + r) * N1v + kblk + c) * 2;
        cp16(base + OFF_AH + so, (const char*)d_A_hi + ka);
        cp16(base + OFF_AL + so, (const char*)d_A_lo + ka);
    }
    // B hi/lo: 256 rows x 8 chunks = 2048 each
#pragma unroll
    for (int i = 0; i < 4; i++) {
        int idx = t + 512 * i;
        int r = idx >> 3, c = (idx & 7) * 8;
        uint32_t so = (uint32_t)(r * ASTRIDE + c) * 2;
        long long kb = ((long long)r * N1v + kblk + c) * 2;
        cp16(base + OFF_BH + so, (const char*)d_y1t_hi + kb);
        cp16(base + OFF_BL + so, (const char*)d_y1t_lo + kb);
    }
}

__global__ void __launch_bounds__(512, 1) pool_gemm_mma() {
    extern __shared__ __align__(16) char smem[];
    uint32_t sbase = smem_to_u32(smem);
    int tid = threadIdx.x, wid = tid >> 5, lid = tid & 31;
    int m0 = blockIdx.y * 128;
    int kbase = blockIdx.x * (N1v / KSPLIT);   // 2048 range
    const int NB = (N1v / KSPLIT) / KB2;       // 32
    int wm = (wid >> 2) * 32;                  // 0..96
    int wn = (wid & 3) * 64;                   // 0..192

    float acc[2][8][4];
#pragma unroll
    for (int mt = 0; mt < 2; mt++)
#pragma unroll
        for (int nt = 0; nt < 8; nt++)
#pragma unroll
            for (int q = 0; q < 4; q++) acc[mt][nt][q] = 0.0f;

    int arow = wm + (lid & 15);
    int acol = (lid >> 4) * 8;
    // B x4 lane map: matrices (nt-pair): m = lid>>3 -> n-oct = m>>1, k-oct = m&1
    int brow4 = wn + ((lid >> 4) & 1) * 8 + (lid & 7);
    int bcol4 = ((lid >> 3) & 1) * 8;

    fill_async(sbase, 0, m0, kbase);        CP_COMMIT();
    fill_async(sbase, 1, m0, kbase + KB2);  CP_COMMIT();

    for (int it = 0; it < NB; it++) {
        CP_WAIT1();
        __syncthreads();
        int s = it & 1;
        uint32_t base = sbase + s * STG2;
#pragma unroll
        for (int k16 = 0; k16 < KB2 / 16; k16++) {
            uint32_t ah[2][4], alo[2][4];
#pragma unroll
            for (int mt = 0; mt < 2; mt++) {
                uint32_t off = (uint32_t)(((arow + mt * 16) * ASTRIDE + k16 * 16 + acol) * 2);
                ldsm_x4(ah[mt],  base + OFF_AH + off);
                ldsm_x4(alo[mt], base + OFF_AL + off);
            }
#pragma unroll
            for (int nt2 = 0; nt2 < 4; nt2++) {
                uint32_t off = (uint32_t)(((brow4 + nt2 * 16) * ASTRIDE + k16 * 16 + bcol4) * 2);
                uint32_t bh4[4], bl4[4];
                ldsm_x4(bh4, base + OFF_BH + off);
                ldsm_x4(bl4, base + OFF_BL + off);
#pragma unroll
                for (int h = 0; h < 2; h++) {
                    int nt = 2 * nt2 + h;
#pragma unroll
                    for (int mt = 0; mt < 2; mt++) {
                        mma_bf16(acc[mt][nt], ah[mt],  bh4 + 2 * h);
                        mma_bf16(acc[mt][nt], alo[mt], bh4 + 2 * h);
                        mma_bf16(acc[mt][nt], ah[mt],  bl4 + 2 * h);
                    }
                }
            }
        }
        __syncthreads();
        if (it + 2 < NB)
            fill_async(sbase, s, m0, kbase + (it + 2) * KB2);
        CP_COMMIT();
    }

    // epilogue: atomic-accumulate into d_T2g slot 0 ([b][m][g], col = g*4+b)
#pragma unroll
    for (int mt = 0; mt < 2; mt++) {
        int m_lo = m0 + wm + mt * 16 + (lid >> 2);
        int m_hi = m_lo + 8;
#pragma unroll
        for (int nt = 0; nt < 8; nt++) {
            int c0 = wn + nt * 8 + (lid & 3) * 2;
            int c1 = c0 + 1;
            atomicAdd(&d_T2g[(c0 & 3) * T2_BOFF + m_lo * 64 + (c0 >> 2)], acc[mt][nt][0]);
            atomicAdd(&d_T2g[(c1 & 3) * T2_BOFF + m_lo * 64 + (c1 >> 2)], acc[mt][nt][1]);
            atomicAdd(&d_T2g[(c0 & 3) * T2_BOFF + m_hi * 64 + (c0 >> 2)], acc[mt][nt][2]);
            atomicAdd(&d_T2g[(c1 & 3) * T2_BOFF + m_hi * 64 + (c1 >> 2)], acc[mt][nt][3]);
        }
    }
}

// ---------------- einsum 2 ----------------
__global__ void einsum2_kernel(const float* __restrict__ W2, const float* __restrict__ b2) {
    __shared__ __align__(16) float sW[64 * 32];
    int t = blockIdx.x * 128 + threadIdx.x;
    int n = t >> 2, b = t & 3;
    float4 acc[8];
#pragma unroll
    for (int q = 0; q < 8; q++) acc[q] = make_float4(0.f, 0.f, 0.f, 0.f);
    for (int k = 0; k < Kv; k++) {
        __syncthreads();
        for (int i = threadIdx.x; i < 2048; i += 128) sW[i] = W2[k * 2048 + i];
        __syncthreads();
        const float* tp = d_T2g + k * T2_SLOT + b * T2_BOFF + n * 64;
        for (int d = 0; d < 64; d++) {
            float tv = __ldg(&tp[d]);
            const float4* w4 = (const float4*)(sW + d * 32);
#pragma unroll
            for (int q = 0; q < 8; q++) {
                float4 w = w4[q];
                acc[q].x += tv * w.x; acc[q].y += tv * w.y;
                acc[q].z += tv * w.z; acc[q].w += tv * w.w;
            }
        }
    }
    float* yp = d_y2 + n * 128 + b;
#pragma unroll
    for (int q = 0; q < 8; q++) {
        int g0 = q * 4;
        yp[(g0 + 0) * 4] = acc[q].x + b2[g0 + 0];
        yp[(g0 + 1) * 4] = acc[q].y + b2[g0 + 1];
        yp[(g0 + 2) * 4] = acc[q].z + b2[g0 + 2];
        yp[(g0 + 3) * 4] = acc[q].w + b2[g0 + 3];
    }
}

// ---------------- FC (split-K) + log_softmax ----------------
__global__ void fc_kernel(const float* __restrict__ fcw) {
    int bc = blockIdx.x;
    int b = bc / 6, c = bc - b * 6;
    int ks = blockIdx.y;
    const float4* w4 = (const float4*)(fcw + (long long)c * 131072);
    const float4* h4 = (const float4*)(d_y2 + b * 131072);
    float s = 0.0f;
    int beg = ks * 4096, end = beg + 4096;
    for (int i = beg + threadIdx.x; i < end; i += 256) {
        float4 a = __ldg(&w4[i]);
        float4 h = h4[i];
        s += a.x * h.x + a.y * h.y + a.z * h.z + a.w * h.w;
    }
    __shared__ float sh[256];
    sh[threadIdx.x] = s;
    __syncthreads();
    for (int off = 128; off > 0; off >>= 1) {
        if (threadIdx.x < off) sh[threadIdx.x] += sh[threadIdx.x + off];
        __syncthreads();
    }
    if (threadIdx.x == 0) atomicAdd(&d_logits[bc], sh[0]);
}

__global__ void lsm_kernel(float* __restrict__ out, const float* __restrict__ fcb) {
    int b = threadIdx.x;
    if (b < Bv) {
        float l[Cv];
        float m = -1e30f;
#pragma unroll
        for (int c = 0; c < Cv; c++) { l[c] = d_logits[b * Cv + c] + fcb[c]; m = fmaxf(m, l[c]); }
        float s = 0.0f;
#pragma unroll
        for (int c = 0; c < Cv; c++) s += expf(l[c] - m);
        float L = logf(s);
#pragma unroll
        for (int c = 0; c < Cv; c++) out[b * Cv + c] = l[c] - m - L;
    }
}

// ---------------- launch ----------------
extern "C" void kernel_launch(void* const* d_in, const int* in_sizes, int n_in,
                              void* d_out, int out_size) {
    const float* x    = (const float*)d_in[0];
    const void*  ei1  = d_in[1];
    const float* ew1  = (const float*)d_in[2];
    const void*  ei2  = d_in[3];
    const float* ew2  = (const float*)d_in[4];
    const float* bmap = (const float*)d_in[5];
    const float* W1   = (const float*)d_in[6];
    const float* b1   = (const float*)d_in[7];
    const float* W2   = (const float*)d_in[8];
    const float* b2   = (const float*)d_in[9];
    const float* fcw  = (const float*)d_in[10];
    const float* fcb  = (const float*)d_in[11];
    float* out = (float*)d_out;

    cudaFuncSetAttribute(pool_gemm_mma, cudaFuncAttributeMaxDynamicSharedMemorySize,
                         SMEM_GEMM_TOTAL);

    zero_detect_kernel<<<T2_SLOT / 256, 256>>>((const int*)ei1);
    aconv_kernel<<<32768, 256>>>(bmap);
    deg12_kernel<<<(E1v + E2v) / 256, 256>>>(ei1, ew1, ei2, ew2);
    scan_kernel<<<1, 1024>>>();
    fill12_kernel<<<(E1v + E2v) / 256, 256>>>(ei1, ew1, ei2, ew2);

    prop1_all<<<512, 256>>>(x);
    einsum1_kernel<<<(N1v * Bv) / 256, 256>>>(W1, b1);

    y1split_kernel<<<dim3(N1v / 32, 256 / 32), dim3(32, 8)>>>();
    pool_gemm_mma<<<dim3(KSPLIT, 32), 512, SMEM_GEMM_TOTAL>>>();

    prop2_all<<<512, 256>>>();
    einsum2_kernel<<<(N2v * Bv) / 128, 128>>>(W2, b2);

    fc_kernel<<<dim3(Bv * Cv, 8), 256>>>(fcw);
    lsm_kernel<<<1, 32>>>(out, fcb);
}